// round 9
// baseline (speedup 1.0000x reference)
#include <cuda_runtime.h>
#include <cuda_bf16.h>
#include <cstdint>

#define NN   50000
#define EE   800000
#define FIN  128
#define H1   8
#define C1   32
#define HC   256
#define CO   10
#define NG   128
#define NEG_SLOPE 0.2f
#define NBLK 196          // ceil(NN/256)

// ---------------- scratch ----------------------------------------------------
__device__ __nv_bfloat16  g_xhb[(size_t)NN * HC];
__device__ __nv_bfloat16  g_h1b[(size_t)NN * HC];
__device__ __nv_bfloat16  g_w1b[(size_t)HC * FIN];
__device__ float g_as1[NN * H1];
__device__ float g_ad1[NN * H1];
__device__ int   g_deg[NN];
__device__ int   g_off[NN + 1];
__device__ int   g_cur[NN];
__device__ int   g_part[NBLK];
__device__ int   g_ssrc[EE];
__device__ float g_xh2[(size_t)NN * 16];
__device__ float g_as2[NN];
__device__ float g_ad2[NN];
__device__ float g_sums[NG * CO];
__device__ float g_cnt[NG];

__device__ __forceinline__ float lrelu(float x) {
    return fmaxf(x, 0.0f) + NEG_SLOPE * fminf(x, 0.0f);
}
__device__ __forceinline__ float elu(float x) {
    return x > 0.0f ? x : (__expf(x) - 1.0f);
}
__device__ __forceinline__ void mma16816(float* d, const uint32_t* a, const uint32_t* b) {
    asm volatile(
        "mma.sync.aligned.m16n8k16.row.col.f32.bf16.bf16.f32 "
        "{%0,%1,%2,%3}, {%4,%5,%6,%7}, {%8,%9}, {%0,%1,%2,%3};"
        : "+f"(d[0]), "+f"(d[1]), "+f"(d[2]), "+f"(d[3])
        : "r"(a[0]), "r"(a[1]), "r"(a[2]), "r"(a[3]), "r"(b[0]), "r"(b[1]));
}
__device__ __forceinline__ void ldsm4(uint32_t& r0, uint32_t& r1, uint32_t& r2,
                                      uint32_t& r3, uint32_t addr) {
    asm volatile("ldmatrix.sync.aligned.m8n8.x4.shared.b16 {%0,%1,%2,%3}, [%4];"
                 : "=r"(r0), "=r"(r1), "=r"(r2), "=r"(r3) : "r"(addr));
}

// ---------------- 0. zero ----------------------------------------------------
__global__ void k_zero() {
    int i = blockIdx.x * blockDim.x + threadIdx.x;
    if (i < NN) g_deg[i] = 0;
    if (i < NG * CO) g_sums[i] = 0.0f;
    if (i < NG) g_cnt[i] = 0.0f;
}

// ---------------- W1 transpose+convert ----------------------------------------
__global__ void k_cvt_w(const float* __restrict__ W1) {
    __shared__ float s[32][33];
    int k0 = blockIdx.x * 32;
    int n0 = blockIdx.y * 32;
    int tx = threadIdx.x, ty = threadIdx.y;
    s[ty][tx] = W1[(size_t)(k0 + ty) * HC + n0 + tx];
    __syncthreads();
    g_w1b[(size_t)(n0 + ty) * FIN + k0 + tx] = __float2bfloat16(s[tx][ty]);
}

// ---------------- GEMM1 HMMA + ldmatrix: CTA tile 64x256, K=128 (R7 cfg) -------
#define G1_ST   136
#define G1_ST2  (G1_ST * 2)
#define G1_ASZ  (64 * G1_ST2)
#define G1_SMEM (G1_ASZ + 256 * G1_ST2)
__global__ void __launch_bounds__(256, 2) k_gemm1(const float* __restrict__ x,
                                                  const float* __restrict__ att_src,
                                                  const float* __restrict__ att_dst) {
    extern __shared__ char smem[];
    char* sA = smem;
    char* sB = smem + G1_ASZ;
    const int tid = threadIdx.x;
    const int wid = tid >> 5;
    const int lane = tid & 31;
    const int bm = blockIdx.x * 64;
    const int mw = wid >> 2;
    const int nw = wid & 3;
    const int g = lane >> 2;
    const int t2 = (lane & 3) * 2;

#pragma unroll
    for (int i = 0; i < 8; i++) {
        int idx = tid + i * 256;
        int row = idx >> 5;
        int c4 = idx & 31;
        float4 v = make_float4(0.f, 0.f, 0.f, 0.f);
        int grow = bm + row;
        if (grow < NN) v = *(const float4*)(x + (size_t)grow * FIN + c4 * 4);
        __nv_bfloat162 b0 = __floats2bfloat162_rn(v.x, v.y);
        __nv_bfloat162 b1 = __floats2bfloat162_rn(v.z, v.w);
        uint2 p = make_uint2(*(uint32_t*)&b0, *(uint32_t*)&b1);
        *(uint2*)(sA + row * G1_ST2 + c4 * 8) = p;
    }
#pragma unroll
    for (int i = 0; i < 16; i++) {
        int idx = tid + i * 256;
        int row = idx >> 4;
        int c16 = idx & 15;
        uint4 v = *(const uint4*)(g_w1b + (size_t)row * FIN + c16 * 8);
        *(uint4*)(sB + row * G1_ST2 + c16 * 16) = v;
    }
    __syncthreads();

    const uint32_t sAu = (uint32_t)__cvta_generic_to_shared(sA);
    const uint32_t sBu = (uint32_t)__cvta_generic_to_shared(sB);
    const int l15 = lane & 15;
    const int kgA = ((lane >> 4) & 1) * 16;
    uint32_t aAddr[2];
#pragma unroll
    for (int mt = 0; mt < 2; mt++)
        aAddr[mt] = sAu + (mw * 32 + mt * 16 + l15) * G1_ST2 + kgA;
    const int rB = (lane & 7) + ((lane >> 4) & 1) * 8;
    const int kgB = ((lane >> 3) & 1) * 16;
    uint32_t bAddr[4];
#pragma unroll
    for (int jp = 0; jp < 4; jp++)
        bAddr[jp] = sBu + (nw * 64 + jp * 16 + rB) * G1_ST2 + kgB;

    float acc[2][8][4];
#pragma unroll
    for (int mt = 0; mt < 2; mt++)
#pragma unroll
        for (int j = 0; j < 8; j++)
#pragma unroll
            for (int q = 0; q < 4; q++) acc[mt][j][q] = 0.f;

#pragma unroll
    for (int kk = 0; kk < 8; kk++) {
        const uint32_t ko = kk * 32;
        uint32_t afr[2][4];
#pragma unroll
        for (int mt = 0; mt < 2; mt++)
            ldsm4(afr[mt][0], afr[mt][1], afr[mt][2], afr[mt][3], aAddr[mt] + ko);
        uint32_t bfr[8][2];
#pragma unroll
        for (int jp = 0; jp < 4; jp++)
            ldsm4(bfr[2 * jp][0], bfr[2 * jp][1], bfr[2 * jp + 1][0], bfr[2 * jp + 1][1],
                  bAddr[jp] + ko);
#pragma unroll
        for (int mt = 0; mt < 2; mt++)
#pragma unroll
            for (int j = 0; j < 8; j++) mma16816(acc[mt][j], afr[mt], bfr[j]);
    }

#pragma unroll
    for (int mt = 0; mt < 2; mt++) {
        const int r0 = bm + mw * 32 + mt * 16 + g;
        const int r1 = r0 + 8;
#pragma unroll
        for (int j = 0; j < 8; j++) {
            const int c = nw * 64 + j * 8 + t2;
            __nv_bfloat162 v0 = __floats2bfloat162_rn(acc[mt][j][0], acc[mt][j][1]);
            __nv_bfloat162 v1 = __floats2bfloat162_rn(acc[mt][j][2], acc[mt][j][3]);
            if (r0 < NN) *(uint32_t*)(g_xhb + (size_t)r0 * HC + c) = *(uint32_t*)&v0;
            if (r1 < NN) *(uint32_t*)(g_xhb + (size_t)r1 * HC + c) = *(uint32_t*)&v1;
        }
#pragma unroll
        for (int hh = 0; hh < 2; hh++) {
            float ps0 = 0.f, pd0 = 0.f, ps1 = 0.f, pd1 = 0.f;
#pragma unroll
            for (int jj = 0; jj < 4; jj++) {
                const int j = hh * 4 + jj;
                const int c = nw * 64 + j * 8 + t2;
                float2 s2 = *(const float2*)(att_src + c);
                float2 d2 = *(const float2*)(att_dst + c);
                ps0 = fmaf(acc[mt][j][0], s2.x, fmaf(acc[mt][j][1], s2.y, ps0));
                pd0 = fmaf(acc[mt][j][0], d2.x, fmaf(acc[mt][j][1], d2.y, pd0));
                ps1 = fmaf(acc[mt][j][2], s2.x, fmaf(acc[mt][j][3], s2.y, ps1));
                pd1 = fmaf(acc[mt][j][2], d2.x, fmaf(acc[mt][j][3], d2.y, pd1));
            }
            ps0 += __shfl_xor_sync(0xffffffffu, ps0, 1);
            pd0 += __shfl_xor_sync(0xffffffffu, pd0, 1);
            ps1 += __shfl_xor_sync(0xffffffffu, ps1, 1);
            pd1 += __shfl_xor_sync(0xffffffffu, pd1, 1);
            ps0 += __shfl_xor_sync(0xffffffffu, ps0, 2);
            pd0 += __shfl_xor_sync(0xffffffffu, pd0, 2);
            ps1 += __shfl_xor_sync(0xffffffffu, ps1, 2);
            pd1 += __shfl_xor_sync(0xffffffffu, pd1, 2);
            const int h = nw * 2 + hh;
            if ((lane & 3) == 0) {
                if (r0 < NN) { g_as1[r0 * H1 + h] = ps0; g_ad1[r0 * H1 + h] = pd0; }
                if (r1 < NN) { g_as1[r1 * H1 + h] = ps1; g_ad1[r1 * H1 + h] = pd1; }
            }
        }
    }
}

// ---------------- CSR build ----------------------------------------------------
__global__ void k_hist(const int* __restrict__ ei, int E) {
    int e = blockIdx.x * blockDim.x + threadIdx.x;
    if (e < E) atomicAdd(&g_deg[ei[E + e]], 1);
}
__global__ void k_scan1() {
    __shared__ int s[256];
    int i = blockIdx.x * 256 + threadIdx.x;
    int v = (i < NN) ? g_deg[i] : 0;
    s[threadIdx.x] = v;
    __syncthreads();
    for (int o = 128; o; o >>= 1) {
        if (threadIdx.x < o) s[threadIdx.x] += s[threadIdx.x + o];
        __syncthreads();
    }
    if (threadIdx.x == 0) g_part[blockIdx.x] = s[0];
}
__global__ void k_scan2() {
    __shared__ int s[256];
    int t = threadIdx.x;
    int v = (t < NBLK) ? g_part[t] : 0;
    s[t] = v;
    __syncthreads();
    for (int o = 1; o < 256; o <<= 1) {
        int u = (t >= o) ? s[t - o] : 0;
        __syncthreads();
        s[t] += u;
        __syncthreads();
    }
    if (t < NBLK) g_part[t] = s[t] - v;
}
__global__ void k_scan3() {
    __shared__ int s[256];
    int t = threadIdx.x;
    int i = blockIdx.x * 256 + t;
    int v = (i < NN) ? g_deg[i] : 0;
    s[t] = v;
    __syncthreads();
    for (int o = 1; o < 256; o <<= 1) {
        int u = (t >= o) ? s[t - o] : 0;
        __syncthreads();
        s[t] += u;
        __syncthreads();
    }
    int base = g_part[blockIdx.x];
    if (i < NN) {
        int off = base + s[t] - v;
        g_off[i] = off;
        g_cur[i] = off;
        if (i == NN - 1) g_off[NN] = base + s[t];
    }
}
__global__ void k_scatter(const int* __restrict__ ei, int E) {
    int e = blockIdx.x * blockDim.x + threadIdx.x;
    if (e < E) {
        int d = ei[E + e];
        int p = atomicAdd(&g_cur[d], 1);
        g_ssrc[p] = ei[e];
    }
}

// ---------------- layer-1 aggregation: TWO warps per node (edge split) ----------
// block = 256 thr = 8 warps = 4 nodes; warp pair (side 0/1) splits edges even/odd
__global__ void k_agg1(const float* __restrict__ b1) {
    __shared__ float comb[4][32][10];   // [node][lane][acc0..7, wsum, pad]
    const int warp = threadIdx.x >> 5;
    const int lane = threadIdx.x & 31;
    const int local = warp >> 1;        // node within block (0..3)
    const int side = warp & 1;          // 0 = even edges + self, 1 = odd edges
    const int n = blockIdx.x * 4 + local;   // NN % 4 == 0, always valid
    const int h = lane >> 2;
    const int q = lane & 3;
    const int vidx = h * 4 + q;
    const uint4* xb = (const uint4*)g_xhb;

    const float ad = g_ad1[n * H1 + h];
    float wsum = 0.f;
    float acc[8];
#pragma unroll
    for (int j = 0; j < 8; j++) acc[j] = 0.f;

    if (side == 0) {   // self loop
        float w = __expf(lrelu(g_as1[n * H1 + h] + ad));
        wsum = w;
        uint4 sv = xb[(size_t)n * 32 + vidx];
        const __nv_bfloat162* bp = (const __nv_bfloat162*)&sv;
#pragma unroll
        for (int j = 0; j < 4; j++) {
            float2 f = __bfloat1622float2(bp[j]);
            acc[2 * j] = w * f.x;
            acc[2 * j + 1] = w * f.y;
        }
    }

    const int end = g_off[n + 1];
    int e = g_off[n] + side;
    // pairs (e, e+2), stride 4
    for (; e + 2 < end; e += 4) {
        const int s0 = g_ssrc[e];
        const int s1 = g_ssrc[e + 2];
        const float a0 = g_as1[s0 * H1 + h];
        const float a1 = g_as1[s1 * H1 + h];
        const uint4 v0 = xb[(size_t)s0 * 32 + vidx];
        const uint4 v1 = xb[(size_t)s1 * 32 + vidx];
        const float w0 = __expf(lrelu(a0 + ad));
        const float w1 = __expf(lrelu(a1 + ad));
        wsum += w0 + w1;
        const __nv_bfloat162* p0 = (const __nv_bfloat162*)&v0;
        const __nv_bfloat162* p1 = (const __nv_bfloat162*)&v1;
#pragma unroll
        for (int j = 0; j < 4; j++) {
            float2 f0 = __bfloat1622float2(p0[j]);
            float2 f1 = __bfloat1622float2(p1[j]);
            acc[2 * j]     = fmaf(w0, f0.x, fmaf(w1, f1.x, acc[2 * j]));
            acc[2 * j + 1] = fmaf(w0, f0.y, fmaf(w1, f1.y, acc[2 * j + 1]));
        }
    }
    if (e < end) {
        const int s0 = g_ssrc[e];
        const float a0 = g_as1[s0 * H1 + h];
        const uint4 v0 = xb[(size_t)s0 * 32 + vidx];
        const float w0 = __expf(lrelu(a0 + ad));
        wsum += w0;
        const __nv_bfloat162* p0 = (const __nv_bfloat162*)&v0;
#pragma unroll
        for (int j = 0; j < 4; j++) {
            float2 f0 = __bfloat1622float2(p0[j]);
            acc[2 * j]     = fmaf(w0, f0.x, acc[2 * j]);
            acc[2 * j + 1] = fmaf(w0, f0.y, acc[2 * j + 1]);
        }
    }

    // combine side1 -> side0 via smem
    if (side == 1) {
#pragma unroll
        for (int j = 0; j < 8; j++) comb[local][lane][j] = acc[j];
        comb[local][lane][8] = wsum;
    }
    __syncthreads();
    if (side == 0) {
#pragma unroll
        for (int j = 0; j < 8; j++) acc[j] += comb[local][lane][j];
        wsum += comb[local][lane][8];
        const float inv = 1.0f / wsum;
        const int c0 = h * C1 + q * 8;
        __nv_bfloat162 ob[4];
#pragma unroll
        for (int j = 0; j < 4; j++) {
            float ox = elu(acc[2 * j] * inv + b1[c0 + 2 * j]);
            float oy = elu(acc[2 * j + 1] * inv + b1[c0 + 2 * j + 1]);
            ob[j] = __floats2bfloat162_rn(ox, oy);
        }
        ((uint4*)g_h1b)[(size_t)n * 32 + vidx] = *(uint4*)ob;
    }
}

// ---------------- GEMM2 HMMA: 128x16x256, fused attention epilogue --------------
#define G2_ST   264
#define G2_ASZ  (128 * G2_ST * 2)
#define G2_BSZ  (16 * G2_ST * 2)
#define G2_SMEM (G2_ASZ + G2_BSZ)
__global__ void __launch_bounds__(256, 2) k_gemm2(const float* __restrict__ W2,
                                                  const float* __restrict__ att_src2,
                                                  const float* __restrict__ att_dst2) {
    extern __shared__ char smem[];
    char* sA = smem;
    char* sB = smem + G2_ASZ;
    const int tid = threadIdx.x;
    const int wid = tid >> 5;
    const int lane = tid & 31;
    const int bm = blockIdx.x * 128;
    const int g = lane >> 2;
    const int t2 = (lane & 3) * 2;

    for (int i = tid; i < G2_BSZ / 4; i += 256) ((uint32_t*)sB)[i] = 0;
#pragma unroll
    for (int i = 0; i < 16; i++) {
        int idx = tid + i * 256;
        int row = idx >> 5;
        int c16 = idx & 31;
        int grow = bm + row;
        uint4 v = make_uint4(0, 0, 0, 0);
        if (grow < NN) v = *(const uint4*)(g_h1b + (size_t)grow * HC + c16 * 8);
        *(uint4*)(sA + row * (G2_ST * 2) + c16 * 16) = v;
    }
    __syncthreads();
    for (int idx = tid; idx < HC * CO; idx += 256) {
        int k = idx / CO;
        int n = idx % CO;
        ((__nv_bfloat16*)sB)[n * G2_ST + k] = __float2bfloat16(W2[idx]);
    }
    __syncthreads();

    float a0c[4] = {0.f, 0.f, 0.f, 0.f};
    float a1c[4] = {0.f, 0.f, 0.f, 0.f};
#pragma unroll
    for (int kk = 0; kk < 16; kk++) {
        const int k0 = kk * 16;
        const int rb = wid * 16;
        uint32_t afr[4];
        afr[0] = *(const uint32_t*)(sA + (rb + g) * (G2_ST * 2) + (k0 + t2) * 2);
        afr[1] = *(const uint32_t*)(sA + (rb + g + 8) * (G2_ST * 2) + (k0 + t2) * 2);
        afr[2] = *(const uint32_t*)(sA + (rb + g) * (G2_ST * 2) + (k0 + 8 + t2) * 2);
        afr[3] = *(const uint32_t*)(sA + (rb + g + 8) * (G2_ST * 2) + (k0 + 8 + t2) * 2);
        uint32_t b0[2], b1[2];
        b0[0] = *(const uint32_t*)(sB + g * (G2_ST * 2) + (k0 + t2) * 2);
        b0[1] = *(const uint32_t*)(sB + g * (G2_ST * 2) + (k0 + 8 + t2) * 2);
        b1[0] = *(const uint32_t*)(sB + (8 + g) * (G2_ST * 2) + (k0 + t2) * 2);
        b1[1] = *(const uint32_t*)(sB + (8 + g) * (G2_ST * 2) + (k0 + 8 + t2) * 2);
        mma16816(a0c, afr, b0);
        mma16816(a1c, afr, b1);
    }

    const int r0 = bm + wid * 16 + g;
    const int r1 = r0 + 8;
    if (r0 < NN) {
        *(float2*)(g_xh2 + (size_t)r0 * 16 + t2) = make_float2(a0c[0], a0c[1]);
        *(float2*)(g_xh2 + (size_t)r0 * 16 + 8 + t2) = make_float2(a1c[0], a1c[1]);
    }
    if (r1 < NN) {
        *(float2*)(g_xh2 + (size_t)r1 * 16 + t2) = make_float2(a0c[2], a0c[3]);
        *(float2*)(g_xh2 + (size_t)r1 * 16 + 8 + t2) = make_float2(a1c[2], a1c[3]);
    }
    float s0x = att_src2[t2], s0y = att_src2[t2 + 1];
    float d0x = att_dst2[t2], d0y = att_dst2[t2 + 1];
    float s1x = 0.f, s1y = 0.f, d1x = 0.f, d1y = 0.f;
    if (t2 == 0) { s1x = att_src2[8]; s1y = att_src2[9]; d1x = att_dst2[8]; d1y = att_dst2[9]; }
    float ps0 = a0c[0] * s0x + a0c[1] * s0y + a1c[0] * s1x + a1c[1] * s1y;
    float pd0 = a0c[0] * d0x + a0c[1] * d0y + a1c[0] * d1x + a1c[1] * d1y;
    float ps1 = a0c[2] * s0x + a0c[3] * s0y + a1c[2] * s1x + a1c[3] * s1y;
    float pd1 = a0c[2] * d0x + a0c[3] * d0y + a1c[2] * d1x + a1c[3] * d1y;
    ps0 += __shfl_xor_sync(0xffffffffu, ps0, 1);
    pd0 += __shfl_xor_sync(0xffffffffu, pd0, 1);
    ps1 += __shfl_xor_sync(0xffffffffu, ps1, 1);
    pd1 += __shfl_xor_sync(0xffffffffu, pd1, 1);
    ps0 += __shfl_xor_sync(0xffffffffu, ps0, 2);
    pd0 += __shfl_xor_sync(0xffffffffu, pd0, 2);
    ps1 += __shfl_xor_sync(0xffffffffu, ps1, 2);
    pd1 += __shfl_xor_sync(0xffffffffu, pd1, 2);
    if ((lane & 3) == 0) {
        if (r0 < NN) { g_as2[r0] = ps0; g_ad2[r0] = pd0; }
        if (r1 < NN) { g_as2[r1] = ps1; g_ad2[r1] = pd1; }
    }
}

// ---------------- layer-2 aggregation ---------------------------------------------
__global__ void k_agg2(const int* __restrict__ batch, const float* __restrict__ b2) {
    int warp = threadIdx.x >> 5;
    int lane = threadIdx.x & 31;
    int n = blockIdx.x * 8 + warp;
    if (n >= NN) return;
    const int half = lane >> 4;
    const int i = lane & 15;
    const float ad = g_ad2[n];
    float wsum = 0.f, acc = 0.f;
    if (half == 0) {
        float w = __expf(lrelu(g_as2[n] + ad));
        wsum = w;
        acc = w * g_xh2[(size_t)n * 16 + i];
    }
    const int beg = g_off[n], end = g_off[n + 1];
    for (int e = beg + half; e < end; e += 2) {
        const int s = g_ssrc[e];
        const float we = __expf(lrelu(g_as2[s] + ad));
        wsum += we;
        acc = fmaf(we, g_xh2[(size_t)s * 16 + i], acc);
    }
    wsum += __shfl_xor_sync(0xffffffffu, wsum, 16);
    acc += __shfl_xor_sync(0xffffffffu, acc, 16);
    if (half == 0 && i < CO) {
        float out = elu(acc / wsum + b2[i]);
        atomicAdd(&g_sums[batch[n] * CO + i], out);
    }
    if (lane == 0) atomicAdd(&g_cnt[batch[n]], 1.0f);
}

// ---------------- mean + log_softmax ----------------------------------------------
__global__ void k_final(float* __restrict__ out) {
    int g = threadIdx.x;
    if (g >= NG) return;
    float inv = 1.0f / fmaxf(g_cnt[g], 1.0f);
    float v[CO];
    float mx = -1e30f;
#pragma unroll
    for (int c = 0; c < CO; c++) {
        v[c] = g_sums[g * CO + c] * inv;
        mx = fmaxf(mx, v[c]);
    }
    float s = 0.f;
#pragma unroll
    for (int c = 0; c < CO; c++) s += __expf(v[c] - mx);
    float lse = logf(s) + mx;
#pragma unroll
    for (int c = 0; c < CO; c++) out[g * CO + c] = v[c] - lse;
}

// ---------------- launcher ----------------------------------------------------------
extern "C" void kernel_launch(void* const* d_in, const int* in_sizes, int n_in,
                              void* d_out, int out_size) {
    const float* x        = (const float*)d_in[0];
    const int*   ei       = (const int*)d_in[1];
    const int*   batch    = (const int*)d_in[2];
    const float* W1       = (const float*)d_in[3];
    const float* att_src1 = (const float*)d_in[4];
    const float* att_dst1 = (const float*)d_in[5];
    const float* b1       = (const float*)d_in[6];
    const float* W2       = (const float*)d_in[7];
    const float* att_src2 = (const float*)d_in[8];
    const float* att_dst2 = (const float*)d_in[9];
    const float* b2       = (const float*)d_in[10];
    float* out = (float*)d_out;
    const int E = in_sizes[1] / 2;

    static cudaStream_t s1 = nullptr;
    static cudaEvent_t e0 = nullptr, e1 = nullptr;
    if (!s1) {
        cudaStreamCreateWithFlags(&s1, cudaStreamNonBlocking);
        cudaEventCreateWithFlags(&e0, cudaEventDisableTiming);
        cudaEventCreateWithFlags(&e1, cudaEventDisableTiming);
        cudaFuncSetAttribute(k_gemm1, cudaFuncAttributeMaxDynamicSharedMemorySize, G1_SMEM);
        cudaFuncSetAttribute(k_gemm2, cudaFuncAttributeMaxDynamicSharedMemorySize, G2_SMEM);
    }

    cudaEventRecord(e0, 0);
    k_zero<<<(NN + 255) / 256, 256>>>();
    k_hist<<<(E + 255) / 256, 256>>>(ei, E);
    cudaStreamWaitEvent(s1, e0, 0);
    k_cvt_w<<<dim3(FIN / 32, HC / 32), dim3(32, 32), 0, s1>>>(W1);
    k_gemm1<<<(NN + 63) / 64, 256, G1_SMEM, s1>>>(x, att_src1, att_dst1);  // 4th launch (profiled)
    cudaEventRecord(e1, s1);
    k_scan1<<<NBLK, 256>>>();
    k_scan2<<<1, 256>>>();
    k_scan3<<<NBLK, 256>>>();
    k_scatter<<<(E + 255) / 256, 256>>>(ei, E);
    cudaStreamWaitEvent(0, e1, 0);
    k_agg1<<<NN / 4, 256>>>(b1);
    k_gemm2<<<(NN + 127) / 128, 256, G2_SMEM>>>(W2, att_src2, att_dst2);
    k_agg2<<<(NN + 7) / 8, 256>>>(batch, b2);
    k_final<<<1, NG>>>(out);
}

// round 10
// speedup vs baseline: 1.4236x; 1.4236x over previous
#include <cuda_runtime.h>
#include <cuda_bf16.h>
#include <cstdint>

#define NN   50000
#define EE   800000
#define FIN  128
#define H1   8
#define C1   32
#define HC   256
#define CO   10
#define NG   128
#define NEG_SLOPE 0.2f
#define NBLK 196          // ceil(NN/256)

// ---------------- scratch ----------------------------------------------------
__device__ __nv_bfloat16  g_xhb[(size_t)NN * HC];
__device__ __nv_bfloat16  g_h1b[(size_t)NN * HC];
__device__ __nv_bfloat16  g_w1b[(size_t)HC * FIN];
__device__ float g_as1[NN * H1];
__device__ float g_ad1[NN * H1];
__device__ int   g_deg[NN];
__device__ int   g_off[NN + 1];
__device__ int   g_cur[NN];
__device__ int   g_part[NBLK];
__device__ int   g_ssrc[EE];
__device__ float g_xh2[(size_t)NN * 16];
__device__ float g_as2[NN];
__device__ float g_ad2[NN];
__device__ float g_sums[NG * CO];
__device__ float g_cnt[NG];

__device__ __forceinline__ float lrelu(float x) {
    return fmaxf(x, 0.0f) + NEG_SLOPE * fminf(x, 0.0f);
}
__device__ __forceinline__ float elu(float x) {
    return x > 0.0f ? x : (__expf(x) - 1.0f);
}
__device__ __forceinline__ void mma16816(float* d, const uint32_t* a, const uint32_t* b) {
    asm volatile(
        "mma.sync.aligned.m16n8k16.row.col.f32.bf16.bf16.f32 "
        "{%0,%1,%2,%3}, {%4,%5,%6,%7}, {%8,%9}, {%0,%1,%2,%3};"
        : "+f"(d[0]), "+f"(d[1]), "+f"(d[2]), "+f"(d[3])
        : "r"(a[0]), "r"(a[1]), "r"(a[2]), "r"(a[3]), "r"(b[0]), "r"(b[1]));
}
__device__ __forceinline__ void ldsm4(uint32_t& r0, uint32_t& r1, uint32_t& r2,
                                      uint32_t& r3, uint32_t addr) {
    asm volatile("ldmatrix.sync.aligned.m8n8.x4.shared.b16 {%0,%1,%2,%3}, [%4];"
                 : "=r"(r0), "=r"(r1), "=r"(r2), "=r"(r3) : "r"(addr));
}

// ---------------- 0. zero ----------------------------------------------------
__global__ void k_zero() {
    int i = blockIdx.x * blockDim.x + threadIdx.x;
    if (i < NN) g_deg[i] = 0;
    if (i < NG * CO) g_sums[i] = 0.0f;
    if (i < NG) g_cnt[i] = 0.0f;
}

// ---------------- W1 transpose+convert ----------------------------------------
__global__ void k_cvt_w(const float* __restrict__ W1) {
    __shared__ float s[32][33];
    int k0 = blockIdx.x * 32;
    int n0 = blockIdx.y * 32;
    int tx = threadIdx.x, ty = threadIdx.y;
    s[ty][tx] = W1[(size_t)(k0 + ty) * HC + n0 + tx];
    __syncthreads();
    g_w1b[(size_t)(n0 + ty) * FIN + k0 + tx] = __float2bfloat16(s[tx][ty]);
}

// ---------------- GEMM1 HMMA + ldmatrix: CTA tile 64x256, K=128 (R7 cfg) -------
#define G1_ST   136
#define G1_ST2  (G1_ST * 2)
#define G1_ASZ  (64 * G1_ST2)
#define G1_SMEM (G1_ASZ + 256 * G1_ST2)
__global__ void __launch_bounds__(256, 2) k_gemm1(const float* __restrict__ x,
                                                  const float* __restrict__ att_src,
                                                  const float* __restrict__ att_dst) {
    extern __shared__ char smem[];
    char* sA = smem;
    char* sB = smem + G1_ASZ;
    const int tid = threadIdx.x;
    const int wid = tid >> 5;
    const int lane = tid & 31;
    const int bm = blockIdx.x * 64;
    const int mw = wid >> 2;
    const int nw = wid & 3;
    const int g = lane >> 2;
    const int t2 = (lane & 3) * 2;

#pragma unroll
    for (int i = 0; i < 8; i++) {
        int idx = tid + i * 256;
        int row = idx >> 5;
        int c4 = idx & 31;
        float4 v = make_float4(0.f, 0.f, 0.f, 0.f);
        int grow = bm + row;
        if (grow < NN) v = *(const float4*)(x + (size_t)grow * FIN + c4 * 4);
        __nv_bfloat162 b0 = __floats2bfloat162_rn(v.x, v.y);
        __nv_bfloat162 b1 = __floats2bfloat162_rn(v.z, v.w);
        uint2 p = make_uint2(*(uint32_t*)&b0, *(uint32_t*)&b1);
        *(uint2*)(sA + row * G1_ST2 + c4 * 8) = p;
    }
#pragma unroll
    for (int i = 0; i < 16; i++) {
        int idx = tid + i * 256;
        int row = idx >> 4;
        int c16 = idx & 15;
        uint4 v = *(const uint4*)(g_w1b + (size_t)row * FIN + c16 * 8);
        *(uint4*)(sB + row * G1_ST2 + c16 * 16) = v;
    }
    __syncthreads();

    const uint32_t sAu = (uint32_t)__cvta_generic_to_shared(sA);
    const uint32_t sBu = (uint32_t)__cvta_generic_to_shared(sB);
    const int l15 = lane & 15;
    const int kgA = ((lane >> 4) & 1) * 16;
    uint32_t aAddr[2];
#pragma unroll
    for (int mt = 0; mt < 2; mt++)
        aAddr[mt] = sAu + (mw * 32 + mt * 16 + l15) * G1_ST2 + kgA;
    const int rB = (lane & 7) + ((lane >> 4) & 1) * 8;
    const int kgB = ((lane >> 3) & 1) * 16;
    uint32_t bAddr[4];
#pragma unroll
    for (int jp = 0; jp < 4; jp++)
        bAddr[jp] = sBu + (nw * 64 + jp * 16 + rB) * G1_ST2 + kgB;

    float acc[2][8][4];
#pragma unroll
    for (int mt = 0; mt < 2; mt++)
#pragma unroll
        for (int j = 0; j < 8; j++)
#pragma unroll
            for (int q = 0; q < 4; q++) acc[mt][j][q] = 0.f;

#pragma unroll
    for (int kk = 0; kk < 8; kk++) {
        const uint32_t ko = kk * 32;
        uint32_t afr[2][4];
#pragma unroll
        for (int mt = 0; mt < 2; mt++)
            ldsm4(afr[mt][0], afr[mt][1], afr[mt][2], afr[mt][3], aAddr[mt] + ko);
        uint32_t bfr[8][2];
#pragma unroll
        for (int jp = 0; jp < 4; jp++)
            ldsm4(bfr[2 * jp][0], bfr[2 * jp][1], bfr[2 * jp + 1][0], bfr[2 * jp + 1][1],
                  bAddr[jp] + ko);
#pragma unroll
        for (int mt = 0; mt < 2; mt++)
#pragma unroll
            for (int j = 0; j < 8; j++) mma16816(acc[mt][j], afr[mt], bfr[j]);
    }

#pragma unroll
    for (int mt = 0; mt < 2; mt++) {
        const int r0 = bm + mw * 32 + mt * 16 + g;
        const int r1 = r0 + 8;
#pragma unroll
        for (int j = 0; j < 8; j++) {
            const int c = nw * 64 + j * 8 + t2;
            __nv_bfloat162 v0 = __floats2bfloat162_rn(acc[mt][j][0], acc[mt][j][1]);
            __nv_bfloat162 v1 = __floats2bfloat162_rn(acc[mt][j][2], acc[mt][j][3]);
            if (r0 < NN) *(uint32_t*)(g_xhb + (size_t)r0 * HC + c) = *(uint32_t*)&v0;
            if (r1 < NN) *(uint32_t*)(g_xhb + (size_t)r1 * HC + c) = *(uint32_t*)&v1;
        }
#pragma unroll
        for (int hh = 0; hh < 2; hh++) {
            float ps0 = 0.f, pd0 = 0.f, ps1 = 0.f, pd1 = 0.f;
#pragma unroll
            for (int jj = 0; jj < 4; jj++) {
                const int j = hh * 4 + jj;
                const int c = nw * 64 + j * 8 + t2;
                float2 s2 = *(const float2*)(att_src + c);
                float2 d2 = *(const float2*)(att_dst + c);
                ps0 = fmaf(acc[mt][j][0], s2.x, fmaf(acc[mt][j][1], s2.y, ps0));
                pd0 = fmaf(acc[mt][j][0], d2.x, fmaf(acc[mt][j][1], d2.y, pd0));
                ps1 = fmaf(acc[mt][j][2], s2.x, fmaf(acc[mt][j][3], s2.y, ps1));
                pd1 = fmaf(acc[mt][j][2], d2.x, fmaf(acc[mt][j][3], d2.y, pd1));
            }
            ps0 += __shfl_xor_sync(0xffffffffu, ps0, 1);
            pd0 += __shfl_xor_sync(0xffffffffu, pd0, 1);
            ps1 += __shfl_xor_sync(0xffffffffu, ps1, 1);
            pd1 += __shfl_xor_sync(0xffffffffu, pd1, 1);
            ps0 += __shfl_xor_sync(0xffffffffu, ps0, 2);
            pd0 += __shfl_xor_sync(0xffffffffu, pd0, 2);
            ps1 += __shfl_xor_sync(0xffffffffu, ps1, 2);
            pd1 += __shfl_xor_sync(0xffffffffu, pd1, 2);
            const int h = nw * 2 + hh;
            if ((lane & 3) == 0) {
                if (r0 < NN) { g_as1[r0 * H1 + h] = ps0; g_ad1[r0 * H1 + h] = pd0; }
                if (r1 < NN) { g_as1[r1 * H1 + h] = ps1; g_ad1[r1 * H1 + h] = pd1; }
            }
        }
    }
}

// ---------------- CSR build ----------------------------------------------------
__global__ void k_hist(const int* __restrict__ ei, int E) {
    int e = blockIdx.x * blockDim.x + threadIdx.x;
    if (e < E) atomicAdd(&g_deg[ei[E + e]], 1);
}
__global__ void k_scan1() {
    __shared__ int s[256];
    int i = blockIdx.x * 256 + threadIdx.x;
    int v = (i < NN) ? g_deg[i] : 0;
    s[threadIdx.x] = v;
    __syncthreads();
    for (int o = 128; o; o >>= 1) {
        if (threadIdx.x < o) s[threadIdx.x] += s[threadIdx.x + o];
        __syncthreads();
    }
    if (threadIdx.x == 0) g_part[blockIdx.x] = s[0];
}
__global__ void k_scan2() {
    __shared__ int s[256];
    int t = threadIdx.x;
    int v = (t < NBLK) ? g_part[t] : 0;
    s[t] = v;
    __syncthreads();
    for (int o = 1; o < 256; o <<= 1) {
        int u = (t >= o) ? s[t - o] : 0;
        __syncthreads();
        s[t] += u;
        __syncthreads();
    }
    if (t < NBLK) g_part[t] = s[t] - v;
}
__global__ void k_scan3() {
    __shared__ int s[256];
    int t = threadIdx.x;
    int i = blockIdx.x * 256 + t;
    int v = (i < NN) ? g_deg[i] : 0;
    s[t] = v;
    __syncthreads();
    for (int o = 1; o < 256; o <<= 1) {
        int u = (t >= o) ? s[t - o] : 0;
        __syncthreads();
        s[t] += u;
        __syncthreads();
    }
    int base = g_part[blockIdx.x];
    if (i < NN) {
        int off = base + s[t] - v;
        g_off[i] = off;
        g_cur[i] = off;
        if (i == NN - 1) g_off[NN] = base + s[t];
    }
}
__global__ void k_scatter(const int* __restrict__ ei, int E) {
    int e = blockIdx.x * blockDim.x + threadIdx.x;
    if (e < E) {
        int d = ei[E + e];
        int p = atomicAdd(&g_cur[d], 1);
        g_ssrc[p] = ei[e];
    }
}

// ---------------- layer-1 aggregation: one warp, TWO nodes interleaved ----------
__device__ __forceinline__ void edge_acc1(int s, float ad, int h, int vidx,
                                          const uint4* xb, float* acc, float& wsum) {
    const float a = g_as1[s * H1 + h];
    const uint4 v = xb[(size_t)s * 32 + vidx];
    const float w = __expf(lrelu(a + ad));
    wsum += w;
    const __nv_bfloat162* p = (const __nv_bfloat162*)&v;
#pragma unroll
    for (int j = 0; j < 4; j++) {
        float2 f = __bfloat1622float2(p[j]);
        acc[2 * j]     = fmaf(w, f.x, acc[2 * j]);
        acc[2 * j + 1] = fmaf(w, f.y, acc[2 * j + 1]);
    }
}

__global__ void k_agg1(const float* __restrict__ b1) {
    const int warp = threadIdx.x >> 5;
    const int lane = threadIdx.x & 31;
    const int nA = (blockIdx.x * 8 + warp) * 2;   // NN % 16 == 0, always valid
    const int nB = nA + 1;
    const int h = lane >> 2;
    const int q = lane & 3;
    const int vidx = h * 4 + q;
    const uint4* xb = (const uint4*)g_xhb;

    const float adA = g_ad1[nA * H1 + h];
    const float adB = g_ad1[nB * H1 + h];
    float accA[8], accB[8];
    float wsumA, wsumB;
    {   // self loops
        float wA = __expf(lrelu(g_as1[nA * H1 + h] + adA));
        float wB = __expf(lrelu(g_as1[nB * H1 + h] + adB));
        wsumA = wA; wsumB = wB;
        uint4 vA = xb[(size_t)nA * 32 + vidx];
        uint4 vB = xb[(size_t)nB * 32 + vidx];
        const __nv_bfloat162* pA = (const __nv_bfloat162*)&vA;
        const __nv_bfloat162* pB = (const __nv_bfloat162*)&vB;
#pragma unroll
        for (int j = 0; j < 4; j++) {
            float2 fA = __bfloat1622float2(pA[j]);
            float2 fB = __bfloat1622float2(pB[j]);
            accA[2 * j] = wA * fA.x; accA[2 * j + 1] = wA * fA.y;
            accB[2 * j] = wB * fB.x; accB[2 * j + 1] = wB * fB.y;
        }
    }

    int eA = g_off[nA];
    const int endA = g_off[nA + 1];
    int eB = endA;                       // g_off[nB] == g_off[nA+1]
    const int endB = g_off[nB + 1];

    // interleaved main loop: 4 independent edge chains in flight
    while (eA + 2 <= endA && eB + 2 <= endB) {
        const int sA0 = g_ssrc[eA], sA1 = g_ssrc[eA + 1];
        const int sB0 = g_ssrc[eB], sB1 = g_ssrc[eB + 1];
        edge_acc1(sA0, adA, h, vidx, xb, accA, wsumA);
        edge_acc1(sB0, adB, h, vidx, xb, accB, wsumB);
        edge_acc1(sA1, adA, h, vidx, xb, accA, wsumA);
        edge_acc1(sB1, adB, h, vidx, xb, accB, wsumB);
        eA += 2; eB += 2;
    }
    // node-A remainder (unroll 2)
    for (; eA + 2 <= endA; eA += 2) {
        const int s0 = g_ssrc[eA], s1 = g_ssrc[eA + 1];
        edge_acc1(s0, adA, h, vidx, xb, accA, wsumA);
        edge_acc1(s1, adA, h, vidx, xb, accA, wsumA);
    }
    // node-B remainder (unroll 2)
    for (; eB + 2 <= endB; eB += 2) {
        const int s0 = g_ssrc[eB], s1 = g_ssrc[eB + 1];
        edge_acc1(s0, adB, h, vidx, xb, accB, wsumB);
        edge_acc1(s1, adB, h, vidx, xb, accB, wsumB);
    }
    if (eA < endA) edge_acc1(g_ssrc[eA], adA, h, vidx, xb, accA, wsumA);
    if (eB < endB) edge_acc1(g_ssrc[eB], adB, h, vidx, xb, accB, wsumB);

    // epilogue: normalize + bias + elu + bf16 store, both nodes
    const int c0 = h * C1 + q * 8;
    float bias[8];
#pragma unroll
    for (int j = 0; j < 8; j++) bias[j] = b1[c0 + j];
    const float invA = 1.0f / wsumA;
    const float invB = 1.0f / wsumB;
    __nv_bfloat162 obA[4], obB[4];
#pragma unroll
    for (int j = 0; j < 4; j++) {
        obA[j] = __floats2bfloat162_rn(elu(accA[2 * j] * invA + bias[2 * j]),
                                       elu(accA[2 * j + 1] * invA + bias[2 * j + 1]));
        obB[j] = __floats2bfloat162_rn(elu(accB[2 * j] * invB + bias[2 * j]),
                                       elu(accB[2 * j + 1] * invB + bias[2 * j + 1]));
    }
    ((uint4*)g_h1b)[(size_t)nA * 32 + vidx] = *(uint4*)obA;
    ((uint4*)g_h1b)[(size_t)nB * 32 + vidx] = *(uint4*)obB;
}

// ---------------- GEMM2 HMMA: 128x16x256, fused attention epilogue --------------
#define G2_ST   264
#define G2_ASZ  (128 * G2_ST * 2)
#define G2_BSZ  (16 * G2_ST * 2)
#define G2_SMEM (G2_ASZ + G2_BSZ)
__global__ void __launch_bounds__(256, 2) k_gemm2(const float* __restrict__ W2,
                                                  const float* __restrict__ att_src2,
                                                  const float* __restrict__ att_dst2) {
    extern __shared__ char smem[];
    char* sA = smem;
    char* sB = smem + G2_ASZ;
    const int tid = threadIdx.x;
    const int wid = tid >> 5;
    const int lane = tid & 31;
    const int bm = blockIdx.x * 128;
    const int g = lane >> 2;
    const int t2 = (lane & 3) * 2;

    for (int i = tid; i < G2_BSZ / 4; i += 256) ((uint32_t*)sB)[i] = 0;
#pragma unroll
    for (int i = 0; i < 16; i++) {
        int idx = tid + i * 256;
        int row = idx >> 5;
        int c16 = idx & 31;
        int grow = bm + row;
        uint4 v = make_uint4(0, 0, 0, 0);
        if (grow < NN) v = *(const uint4*)(g_h1b + (size_t)grow * HC + c16 * 8);
        *(uint4*)(sA + row * (G2_ST * 2) + c16 * 16) = v;
    }
    __syncthreads();
    for (int idx = tid; idx < HC * CO; idx += 256) {
        int k = idx / CO;
        int n = idx % CO;
        ((__nv_bfloat16*)sB)[n * G2_ST + k] = __float2bfloat16(W2[idx]);
    }
    __syncthreads();

    float a0c[4] = {0.f, 0.f, 0.f, 0.f};
    float a1c[4] = {0.f, 0.f, 0.f, 0.f};
#pragma unroll
    for (int kk = 0; kk < 16; kk++) {
        const int k0 = kk * 16;
        const int rb = wid * 16;
        uint32_t afr[4];
        afr[0] = *(const uint32_t*)(sA + (rb + g) * (G2_ST * 2) + (k0 + t2) * 2);
        afr[1] = *(const uint32_t*)(sA + (rb + g + 8) * (G2_ST * 2) + (k0 + t2) * 2);
        afr[2] = *(const uint32_t*)(sA + (rb + g) * (G2_ST * 2) + (k0 + 8 + t2) * 2);
        afr[3] = *(const uint32_t*)(sA + (rb + g + 8) * (G2_ST * 2) + (k0 + 8 + t2) * 2);
        uint32_t b0[2], b1[2];
        b0[0] = *(const uint32_t*)(sB + g * (G2_ST * 2) + (k0 + t2) * 2);
        b0[1] = *(const uint32_t*)(sB + g * (G2_ST * 2) + (k0 + 8 + t2) * 2);
        b1[0] = *(const uint32_t*)(sB + (8 + g) * (G2_ST * 2) + (k0 + t2) * 2);
        b1[1] = *(const uint32_t*)(sB + (8 + g) * (G2_ST * 2) + (k0 + 8 + t2) * 2);
        mma16816(a0c, afr, b0);
        mma16816(a1c, afr, b1);
    }

    const int r0 = bm + wid * 16 + g;
    const int r1 = r0 + 8;
    if (r0 < NN) {
        *(float2*)(g_xh2 + (size_t)r0 * 16 + t2) = make_float2(a0c[0], a0c[1]);
        *(float2*)(g_xh2 + (size_t)r0 * 16 + 8 + t2) = make_float2(a1c[0], a1c[1]);
    }
    if (r1 < NN) {
        *(float2*)(g_xh2 + (size_t)r1 * 16 + t2) = make_float2(a0c[2], a0c[3]);
        *(float2*)(g_xh2 + (size_t)r1 * 16 + 8 + t2) = make_float2(a1c[2], a1c[3]);
    }
    float s0x = att_src2[t2], s0y = att_src2[t2 + 1];
    float d0x = att_dst2[t2], d0y = att_dst2[t2 + 1];
    float s1x = 0.f, s1y = 0.f, d1x = 0.f, d1y = 0.f;
    if (t2 == 0) { s1x = att_src2[8]; s1y = att_src2[9]; d1x = att_dst2[8]; d1y = att_dst2[9]; }
    float ps0 = a0c[0] * s0x + a0c[1] * s0y + a1c[0] * s1x + a1c[1] * s1y;
    float pd0 = a0c[0] * d0x + a0c[1] * d0y + a1c[0] * d1x + a1c[1] * d1y;
    float ps1 = a0c[2] * s0x + a0c[3] * s0y + a1c[2] * s1x + a1c[3] * s1y;
    float pd1 = a0c[2] * d0x + a0c[3] * d0y + a1c[2] * d1x + a1c[3] * d1y;
    ps0 += __shfl_xor_sync(0xffffffffu, ps0, 1);
    pd0 += __shfl_xor_sync(0xffffffffu, pd0, 1);
    ps1 += __shfl_xor_sync(0xffffffffu, ps1, 1);
    pd1 += __shfl_xor_sync(0xffffffffu, pd1, 1);
    ps0 += __shfl_xor_sync(0xffffffffu, ps0, 2);
    pd0 += __shfl_xor_sync(0xffffffffu, pd0, 2);
    ps1 += __shfl_xor_sync(0xffffffffu, ps1, 2);
    pd1 += __shfl_xor_sync(0xffffffffu, pd1, 2);
    if ((lane & 3) == 0) {
        if (r0 < NN) { g_as2[r0] = ps0; g_ad2[r0] = pd0; }
        if (r1 < NN) { g_as2[r1] = ps1; g_ad2[r1] = pd1; }
    }
}

// ---------------- layer-2 aggregation ---------------------------------------------
__global__ void k_agg2(const int* __restrict__ batch, const float* __restrict__ b2) {
    int warp = threadIdx.x >> 5;
    int lane = threadIdx.x & 31;
    int n = blockIdx.x * 8 + warp;
    if (n >= NN) return;
    const int half = lane >> 4;
    const int i = lane & 15;
    const float ad = g_ad2[n];
    float wsum = 0.f, acc = 0.f;
    if (half == 0) {
        float w = __expf(lrelu(g_as2[n] + ad));
        wsum = w;
        acc = w * g_xh2[(size_t)n * 16 + i];
    }
    const int beg = g_off[n], end = g_off[n + 1];
    for (int e = beg + half; e < end; e += 2) {
        const int s = g_ssrc[e];
        const float we = __expf(lrelu(g_as2[s] + ad));
        wsum += we;
        acc = fmaf(we, g_xh2[(size_t)s * 16 + i], acc);
    }
    wsum += __shfl_xor_sync(0xffffffffu, wsum, 16);
    acc += __shfl_xor_sync(0xffffffffu, acc, 16);
    if (half == 0 && i < CO) {
        float out = elu(acc / wsum + b2[i]);
        atomicAdd(&g_sums[batch[n] * CO + i], out);
    }
    if (lane == 0) atomicAdd(&g_cnt[batch[n]], 1.0f);
}

// ---------------- mean + log_softmax ----------------------------------------------
__global__ void k_final(float* __restrict__ out) {
    int g = threadIdx.x;
    if (g >= NG) return;
    float inv = 1.0f / fmaxf(g_cnt[g], 1.0f);
    float v[CO];
    float mx = -1e30f;
#pragma unroll
    for (int c = 0; c < CO; c++) {
        v[c] = g_sums[g * CO + c] * inv;
        mx = fmaxf(mx, v[c]);
    }
    float s = 0.f;
#pragma unroll
    for (int c = 0; c < CO; c++) s += __expf(v[c] - mx);
    float lse = logf(s) + mx;
#pragma unroll
    for (int c = 0; c < CO; c++) out[g * CO + c] = v[c] - lse;
}

// ---------------- launcher ----------------------------------------------------------
extern "C" void kernel_launch(void* const* d_in, const int* in_sizes, int n_in,
                              void* d_out, int out_size) {
    const float* x        = (const float*)d_in[0];
    const int*   ei       = (const int*)d_in[1];
    const int*   batch    = (const int*)d_in[2];
    const float* W1       = (const float*)d_in[3];
    const float* att_src1 = (const float*)d_in[4];
    const float* att_dst1 = (const float*)d_in[5];
    const float* b1       = (const float*)d_in[6];
    const float* W2       = (const float*)d_in[7];
    const float* att_src2 = (const float*)d_in[8];
    const float* att_dst2 = (const float*)d_in[9];
    const float* b2       = (const float*)d_in[10];
    float* out = (float*)d_out;
    const int E = in_sizes[1] / 2;

    static cudaStream_t s1 = nullptr;
    static cudaEvent_t e0 = nullptr, e1 = nullptr;
    if (!s1) {
        cudaStreamCreateWithFlags(&s1, cudaStreamNonBlocking);
        cudaEventCreateWithFlags(&e0, cudaEventDisableTiming);
        cudaEventCreateWithFlags(&e1, cudaEventDisableTiming);
        cudaFuncSetAttribute(k_gemm1, cudaFuncAttributeMaxDynamicSharedMemorySize, G1_SMEM);
        cudaFuncSetAttribute(k_gemm2, cudaFuncAttributeMaxDynamicSharedMemorySize, G2_SMEM);
    }

    cudaEventRecord(e0, 0);
    k_zero<<<(NN + 255) / 256, 256>>>();
    k_hist<<<(E + 255) / 256, 256>>>(ei, E);
    cudaStreamWaitEvent(s1, e0, 0);
    k_cvt_w<<<dim3(FIN / 32, HC / 32), dim3(32, 32), 0, s1>>>(W1);
    k_gemm1<<<(NN + 63) / 64, 256, G1_SMEM, s1>>>(x, att_src1, att_dst1);  // 4th launch (profiled)
    cudaEventRecord(e1, s1);
    k_scan1<<<NBLK, 256>>>();
    k_scan2<<<1, 256>>>();
    k_scan3<<<NBLK, 256>>>();
    k_scatter<<<(E + 255) / 256, 256>>>(ei, E);
    cudaStreamWaitEvent(0, e1, 0);
    k_agg1<<<NN / 16, 256>>>(b1);
    k_gemm2<<<(NN + 127) / 128, 256, G2_SMEM>>>(W2, att_src2, att_dst2);
    k_agg2<<<(NN + 7) / 8, 256>>>(batch, b2);
    k_final<<<1, NG>>>(out);
}

// round 11
// speedup vs baseline: 1.5137x; 1.0633x over previous
#include <cuda_runtime.h>
#include <cuda_bf16.h>
#include <cstdint>

#define NN   50000
#define EE   800000
#define FIN  128
#define H1   8
#define C1   32
#define HC   256
#define CO   10
#define NG   128
#define NEG_SLOPE 0.2f
#define NBLK 196          // ceil(NN/256)

// ---------------- scratch ----------------------------------------------------
__device__ __nv_bfloat16  g_xhb[(size_t)NN * HC];
__device__ __nv_bfloat16  g_h1b[(size_t)NN * HC];
__device__ __nv_bfloat16  g_w1b[(size_t)HC * FIN];
__device__ float g_as1[NN * H1];
__device__ float g_ad1[NN * H1];
__device__ int   g_deg[NN];
__device__ int   g_off[NN + 1];
__device__ int   g_cur[NN];
__device__ int   g_part[NBLK];
__device__ int   g_ssrc[EE];
__device__ float g_xh2[(size_t)NN * 16];
__device__ float g_as2[NN];
__device__ float g_ad2[NN];
__device__ float g_sums[NG * CO];
__device__ float g_cnt[NG];

__device__ __forceinline__ float elu(float x) {
    return x > 0.0f ? x : (__expf(x) - 1.0f);
}
// exp(leaky_relu(x, 0.2)) = 2^(0.6*log2e*x + 0.4*log2e*|x|); |x| is a free modifier
__device__ __forceinline__ float exp_lrelu(float x) {
    float t = fmaf(0.57707802f, fabsf(x), 0.86561702f * x);
    float w;
    asm("ex2.approx.f32 %0, %1;" : "=f"(w) : "f"(t));
    return w;
}
__device__ __forceinline__ float lrelu(float x) {
    return fmaxf(x, 0.0f) + NEG_SLOPE * fminf(x, 0.0f);
}
__device__ __forceinline__ void mma16816(float* d, const uint32_t* a, const uint32_t* b) {
    asm volatile(
        "mma.sync.aligned.m16n8k16.row.col.f32.bf16.bf16.f32 "
        "{%0,%1,%2,%3}, {%4,%5,%6,%7}, {%8,%9}, {%0,%1,%2,%3};"
        : "+f"(d[0]), "+f"(d[1]), "+f"(d[2]), "+f"(d[3])
        : "r"(a[0]), "r"(a[1]), "r"(a[2]), "r"(a[3]), "r"(b[0]), "r"(b[1]));
}
__device__ __forceinline__ void ldsm4(uint32_t& r0, uint32_t& r1, uint32_t& r2,
                                      uint32_t& r3, uint32_t addr) {
    asm volatile("ldmatrix.sync.aligned.m8n8.x4.shared.b16 {%0,%1,%2,%3}, [%4];"
                 : "=r"(r0), "=r"(r1), "=r"(r2), "=r"(r3) : "r"(addr));
}

// ---------------- 0. zero ----------------------------------------------------
__global__ void k_zero() {
    int i = blockIdx.x * blockDim.x + threadIdx.x;
    if (i < NN) g_deg[i] = 0;
    if (i < NG * CO) g_sums[i] = 0.0f;
    if (i < NG) g_cnt[i] = 0.0f;
}

// ---------------- W1 transpose+convert ----------------------------------------
__global__ void k_cvt_w(const float* __restrict__ W1) {
    __shared__ float s[32][33];
    int k0 = blockIdx.x * 32;
    int n0 = blockIdx.y * 32;
    int tx = threadIdx.x, ty = threadIdx.y;
    s[ty][tx] = W1[(size_t)(k0 + ty) * HC + n0 + tx];
    __syncthreads();
    g_w1b[(size_t)(n0 + ty) * FIN + k0 + tx] = __float2bfloat16(s[tx][ty]);
}

// ---------------- GEMM1 HMMA + ldmatrix: CTA tile 64x256, K=128 ----------------
#define G1_ST   136
#define G1_ST2  (G1_ST * 2)
#define G1_ASZ  (64 * G1_ST2)
#define G1_SMEM (G1_ASZ + 256 * G1_ST2)
__global__ void __launch_bounds__(256, 2) k_gemm1(const float* __restrict__ x,
                                                  const float* __restrict__ att_src,
                                                  const float* __restrict__ att_dst) {
    extern __shared__ char smem[];
    char* sA = smem;
    char* sB = smem + G1_ASZ;
    const int tid = threadIdx.x;
    const int wid = tid >> 5;
    const int lane = tid & 31;
    const int bm = blockIdx.x * 64;
    const int mw = wid >> 2;
    const int nw = wid & 3;
    const int g = lane >> 2;
    const int t2 = (lane & 3) * 2;

#pragma unroll
    for (int i = 0; i < 8; i++) {
        int idx = tid + i * 256;
        int row = idx >> 5;
        int c4 = idx & 31;
        float4 v = make_float4(0.f, 0.f, 0.f, 0.f);
        int grow = bm + row;
        if (grow < NN) v = *(const float4*)(x + (size_t)grow * FIN + c4 * 4);
        __nv_bfloat162 b0 = __floats2bfloat162_rn(v.x, v.y);
        __nv_bfloat162 b1 = __floats2bfloat162_rn(v.z, v.w);
        uint2 p = make_uint2(*(uint32_t*)&b0, *(uint32_t*)&b1);
        *(uint2*)(sA + row * G1_ST2 + c4 * 8) = p;
    }
#pragma unroll
    for (int i = 0; i < 16; i++) {
        int idx = tid + i * 256;
        int row = idx >> 4;
        int c16 = idx & 15;
        uint4 v = *(const uint4*)(g_w1b + (size_t)row * FIN + c16 * 8);
        *(uint4*)(sB + row * G1_ST2 + c16 * 16) = v;
    }
    __syncthreads();

    const uint32_t sAu = (uint32_t)__cvta_generic_to_shared(sA);
    const uint32_t sBu = (uint32_t)__cvta_generic_to_shared(sB);
    const int l15 = lane & 15;
    const int kgA = ((lane >> 4) & 1) * 16;
    uint32_t aAddr[2];
#pragma unroll
    for (int mt = 0; mt < 2; mt++)
        aAddr[mt] = sAu + (mw * 32 + mt * 16 + l15) * G1_ST2 + kgA;
    const int rB = (lane & 7) + ((lane >> 4) & 1) * 8;
    const int kgB = ((lane >> 3) & 1) * 16;
    uint32_t bAddr[4];
#pragma unroll
    for (int jp = 0; jp < 4; jp++)
        bAddr[jp] = sBu + (nw * 64 + jp * 16 + rB) * G1_ST2 + kgB;

    float acc[2][8][4];
#pragma unroll
    for (int mt = 0; mt < 2; mt++)
#pragma unroll
        for (int j = 0; j < 8; j++)
#pragma unroll
            for (int q = 0; q < 4; q++) acc[mt][j][q] = 0.f;

#pragma unroll
    for (int kk = 0; kk < 8; kk++) {
        const uint32_t ko = kk * 32;
        uint32_t afr[2][4];
#pragma unroll
        for (int mt = 0; mt < 2; mt++)
            ldsm4(afr[mt][0], afr[mt][1], afr[mt][2], afr[mt][3], aAddr[mt] + ko);
        uint32_t bfr[8][2];
#pragma unroll
        for (int jp = 0; jp < 4; jp++)
            ldsm4(bfr[2 * jp][0], bfr[2 * jp][1], bfr[2 * jp + 1][0], bfr[2 * jp + 1][1],
                  bAddr[jp] + ko);
#pragma unroll
        for (int mt = 0; mt < 2; mt++)
#pragma unroll
            for (int j = 0; j < 8; j++) mma16816(acc[mt][j], afr[mt], bfr[j]);
    }

#pragma unroll
    for (int mt = 0; mt < 2; mt++) {
        const int r0 = bm + mw * 32 + mt * 16 + g;
        const int r1 = r0 + 8;
#pragma unroll
        for (int j = 0; j < 8; j++) {
            const int c = nw * 64 + j * 8 + t2;
            __nv_bfloat162 v0 = __floats2bfloat162_rn(acc[mt][j][0], acc[mt][j][1]);
            __nv_bfloat162 v1 = __floats2bfloat162_rn(acc[mt][j][2], acc[mt][j][3]);
            if (r0 < NN) *(uint32_t*)(g_xhb + (size_t)r0 * HC + c) = *(uint32_t*)&v0;
            if (r1 < NN) *(uint32_t*)(g_xhb + (size_t)r1 * HC + c) = *(uint32_t*)&v1;
        }
#pragma unroll
        for (int hh = 0; hh < 2; hh++) {
            float ps0 = 0.f, pd0 = 0.f, ps1 = 0.f, pd1 = 0.f;
#pragma unroll
            for (int jj = 0; jj < 4; jj++) {
                const int j = hh * 4 + jj;
                const int c = nw * 64 + j * 8 + t2;
                float2 s2 = *(const float2*)(att_src + c);
                float2 d2 = *(const float2*)(att_dst + c);
                ps0 = fmaf(acc[mt][j][0], s2.x, fmaf(acc[mt][j][1], s2.y, ps0));
                pd0 = fmaf(acc[mt][j][0], d2.x, fmaf(acc[mt][j][1], d2.y, pd0));
                ps1 = fmaf(acc[mt][j][2], s2.x, fmaf(acc[mt][j][3], s2.y, ps1));
                pd1 = fmaf(acc[mt][j][2], d2.x, fmaf(acc[mt][j][3], d2.y, pd1));
            }
            ps0 += __shfl_xor_sync(0xffffffffu, ps0, 1);
            pd0 += __shfl_xor_sync(0xffffffffu, pd0, 1);
            ps1 += __shfl_xor_sync(0xffffffffu, ps1, 1);
            pd1 += __shfl_xor_sync(0xffffffffu, pd1, 1);
            ps0 += __shfl_xor_sync(0xffffffffu, ps0, 2);
            pd0 += __shfl_xor_sync(0xffffffffu, pd0, 2);
            ps1 += __shfl_xor_sync(0xffffffffu, ps1, 2);
            pd1 += __shfl_xor_sync(0xffffffffu, pd1, 2);
            const int h = nw * 2 + hh;
            if ((lane & 3) == 0) {
                if (r0 < NN) { g_as1[r0 * H1 + h] = ps0; g_ad1[r0 * H1 + h] = pd0; }
                if (r1 < NN) { g_as1[r1 * H1 + h] = ps1; g_ad1[r1 * H1 + h] = pd1; }
            }
        }
    }
}

// ---------------- CSR build ----------------------------------------------------
__global__ void k_hist(const int* __restrict__ ei, int E) {
    int e = blockIdx.x * blockDim.x + threadIdx.x;
    if (e < E) atomicAdd(&g_deg[ei[E + e]], 1);
}
__global__ void k_scan1() {
    __shared__ int s[256];
    int i = blockIdx.x * 256 + threadIdx.x;
    int v = (i < NN) ? g_deg[i] : 0;
    s[threadIdx.x] = v;
    __syncthreads();
    for (int o = 128; o; o >>= 1) {
        if (threadIdx.x < o) s[threadIdx.x] += s[threadIdx.x + o];
        __syncthreads();
    }
    if (threadIdx.x == 0) g_part[blockIdx.x] = s[0];
}
__global__ void k_scan2() {
    __shared__ int s[256];
    int t = threadIdx.x;
    int v = (t < NBLK) ? g_part[t] : 0;
    s[t] = v;
    __syncthreads();
    for (int o = 1; o < 256; o <<= 1) {
        int u = (t >= o) ? s[t - o] : 0;
        __syncthreads();
        s[t] += u;
        __syncthreads();
    }
    if (t < NBLK) g_part[t] = s[t] - v;
}
__global__ void k_scan3() {
    __shared__ int s[256];
    int t = threadIdx.x;
    int i = blockIdx.x * 256 + t;
    int v = (i < NN) ? g_deg[i] : 0;
    s[t] = v;
    __syncthreads();
    for (int o = 1; o < 256; o <<= 1) {
        int u = (t >= o) ? s[t - o] : 0;
        __syncthreads();
        s[t] += u;
        __syncthreads();
    }
    int base = g_part[blockIdx.x];
    if (i < NN) {
        int off = base + s[t] - v;
        g_off[i] = off;
        g_cur[i] = off;
        if (i == NN - 1) g_off[NN] = base + s[t];
    }
}
__global__ void k_scatter(const int* __restrict__ ei, int E) {
    int e = blockIdx.x * blockDim.x + threadIdx.x;
    if (e < E) {
        int d = ei[E + e];
        int p = atomicAdd(&g_cur[d], 1);
        g_ssrc[p] = ei[e];
    }
}

// ---------------- layer-1 aggregation: bf16x2 HFMA2 accumulation ----------------
// one warp, two nodes interleaved; acc in bf16x2 (4 regs/node), wsum fp32
__device__ __forceinline__ void edge_acc1(int s, float ad, int h, int vidx,
                                          const uint4* xb, __nv_bfloat162* acc,
                                          float& wsum) {
    const float a = g_as1[s * H1 + h];
    const uint4 v = xb[(size_t)s * 32 + vidx];
    const float w = exp_lrelu(a + ad);
    wsum += w;
    const __nv_bfloat162 w2 = __float2bfloat162_rn(w);
    const __nv_bfloat162* p = (const __nv_bfloat162*)&v;
#pragma unroll
    for (int j = 0; j < 4; j++) acc[j] = __hfma2(w2, p[j], acc[j]);
}

__global__ void k_agg1(const float* __restrict__ b1) {
    const int warp = threadIdx.x >> 5;
    const int lane = threadIdx.x & 31;
    const int nA = (blockIdx.x * 8 + warp) * 2;
    const int nB = nA + 1;
    const int h = lane >> 2;
    const int q = lane & 3;
    const int vidx = h * 4 + q;
    const uint4* xb = (const uint4*)g_xhb;

    const float adA = g_ad1[nA * H1 + h];
    const float adB = g_ad1[nB * H1 + h];
    __nv_bfloat162 accA[4], accB[4];
    float wsumA, wsumB;
    {   // self loops
        float wA = exp_lrelu(g_as1[nA * H1 + h] + adA);
        float wB = exp_lrelu(g_as1[nB * H1 + h] + adB);
        wsumA = wA; wsumB = wB;
        __nv_bfloat162 wA2 = __float2bfloat162_rn(wA);
        __nv_bfloat162 wB2 = __float2bfloat162_rn(wB);
        uint4 vA = xb[(size_t)nA * 32 + vidx];
        uint4 vB = xb[(size_t)nB * 32 + vidx];
        const __nv_bfloat162* pA = (const __nv_bfloat162*)&vA;
        const __nv_bfloat162* pB = (const __nv_bfloat162*)&vB;
#pragma unroll
        for (int j = 0; j < 4; j++) {
            accA[j] = __hmul2(wA2, pA[j]);
            accB[j] = __hmul2(wB2, pB[j]);
        }
    }

    int eA = g_off[nA];
    const int endA = g_off[nA + 1];
    int eB = endA;
    const int endB = g_off[nB + 1];

    while (eA + 2 <= endA && eB + 2 <= endB) {
        const int sA0 = g_ssrc[eA], sA1 = g_ssrc[eA + 1];
        const int sB0 = g_ssrc[eB], sB1 = g_ssrc[eB + 1];
        edge_acc1(sA0, adA, h, vidx, xb, accA, wsumA);
        edge_acc1(sB0, adB, h, vidx, xb, accB, wsumB);
        edge_acc1(sA1, adA, h, vidx, xb, accA, wsumA);
        edge_acc1(sB1, adB, h, vidx, xb, accB, wsumB);
        eA += 2; eB += 2;
    }
    for (; eA + 2 <= endA; eA += 2) {
        const int s0 = g_ssrc[eA], s1 = g_ssrc[eA + 1];
        edge_acc1(s0, adA, h, vidx, xb, accA, wsumA);
        edge_acc1(s1, adA, h, vidx, xb, accA, wsumA);
    }
    for (; eB + 2 <= endB; eB += 2) {
        const int s0 = g_ssrc[eB], s1 = g_ssrc[eB + 1];
        edge_acc1(s0, adB, h, vidx, xb, accB, wsumB);
        edge_acc1(s1, adB, h, vidx, xb, accB, wsumB);
    }
    if (eA < endA) edge_acc1(g_ssrc[eA], adA, h, vidx, xb, accA, wsumA);
    if (eB < endB) edge_acc1(g_ssrc[eB], adB, h, vidx, xb, accB, wsumB);

    // epilogue: fp32 normalize + bias + elu + bf16 store
    const int c0 = h * C1 + q * 8;
    float bias[8];
#pragma unroll
    for (int j = 0; j < 8; j++) bias[j] = b1[c0 + j];
    const float invA = 1.0f / wsumA;
    const float invB = 1.0f / wsumB;
    __nv_bfloat162 obA[4], obB[4];
#pragma unroll
    for (int j = 0; j < 4; j++) {
        float2 fA = __bfloat1622float2(accA[j]);
        float2 fB = __bfloat1622float2(accB[j]);
        obA[j] = __floats2bfloat162_rn(elu(fA.x * invA + bias[2 * j]),
                                       elu(fA.y * invA + bias[2 * j + 1]));
        obB[j] = __floats2bfloat162_rn(elu(fB.x * invB + bias[2 * j]),
                                       elu(fB.y * invB + bias[2 * j + 1]));
    }
    ((uint4*)g_h1b)[(size_t)nA * 32 + vidx] = *(uint4*)obA;
    ((uint4*)g_h1b)[(size_t)nB * 32 + vidx] = *(uint4*)obB;
}

// ---------------- GEMM2 HMMA: 128x16x256, fused attention epilogue --------------
#define G2_ST   264
#define G2_ASZ  (128 * G2_ST * 2)
#define G2_BSZ  (16 * G2_ST * 2)
#define G2_SMEM (G2_ASZ + G2_BSZ)
__global__ void __launch_bounds__(256, 2) k_gemm2(const float* __restrict__ W2,
                                                  const float* __restrict__ att_src2,
                                                  const float* __restrict__ att_dst2) {
    extern __shared__ char smem[];
    char* sA = smem;
    char* sB = smem + G2_ASZ;
    const int tid = threadIdx.x;
    const int wid = tid >> 5;
    const int lane = tid & 31;
    const int bm = blockIdx.x * 128;
    const int g = lane >> 2;
    const int t2 = (lane & 3) * 2;

    for (int i = tid; i < G2_BSZ / 4; i += 256) ((uint32_t*)sB)[i] = 0;
#pragma unroll
    for (int i = 0; i < 16; i++) {
        int idx = tid + i * 256;
        int row = idx >> 5;
        int c16 = idx & 31;
        int grow = bm + row;
        uint4 v = make_uint4(0, 0, 0, 0);
        if (grow < NN) v = *(const uint4*)(g_h1b + (size_t)grow * HC + c16 * 8);
        *(uint4*)(sA + row * (G2_ST * 2) + c16 * 16) = v;
    }
    __syncthreads();
    for (int idx = tid; idx < HC * CO; idx += 256) {
        int k = idx / CO;
        int n = idx % CO;
        ((__nv_bfloat16*)sB)[n * G2_ST + k] = __float2bfloat16(W2[idx]);
    }
    __syncthreads();

    float a0c[4] = {0.f, 0.f, 0.f, 0.f};
    float a1c[4] = {0.f, 0.f, 0.f, 0.f};
#pragma unroll
    for (int kk = 0; kk < 16; kk++) {
        const int k0 = kk * 16;
        const int rb = wid * 16;
        uint32_t afr[4];
        afr[0] = *(const uint32_t*)(sA + (rb + g) * (G2_ST * 2) + (k0 + t2) * 2);
        afr[1] = *(const uint32_t*)(sA + (rb + g + 8) * (G2_ST * 2) + (k0 + t2) * 2);
        afr[2] = *(const uint32_t*)(sA + (rb + g) * (G2_ST * 2) + (k0 + 8 + t2) * 2);
        afr[3] = *(const uint32_t*)(sA + (rb + g + 8) * (G2_ST * 2) + (k0 + 8 + t2) * 2);
        uint32_t b0[2], b1[2];
        b0[0] = *(const uint32_t*)(sB + g * (G2_ST * 2) + (k0 + t2) * 2);
        b0[1] = *(const uint32_t*)(sB + g * (G2_ST * 2) + (k0 + 8 + t2) * 2);
        b1[0] = *(const uint32_t*)(sB + (8 + g) * (G2_ST * 2) + (k0 + t2) * 2);
        b1[1] = *(const uint32_t*)(sB + (8 + g) * (G2_ST * 2) + (k0 + 8 + t2) * 2);
        mma16816(a0c, afr, b0);
        mma16816(a1c, afr, b1);
    }

    const int r0 = bm + wid * 16 + g;
    const int r1 = r0 + 8;
    if (r0 < NN) {
        *(float2*)(g_xh2 + (size_t)r0 * 16 + t2) = make_float2(a0c[0], a0c[1]);
        *(float2*)(g_xh2 + (size_t)r0 * 16 + 8 + t2) = make_float2(a1c[0], a1c[1]);
    }
    if (r1 < NN) {
        *(float2*)(g_xh2 + (size_t)r1 * 16 + t2) = make_float2(a0c[2], a0c[3]);
        *(float2*)(g_xh2 + (size_t)r1 * 16 + 8 + t2) = make_float2(a1c[2], a1c[3]);
    }
    float s0x = att_src2[t2], s0y = att_src2[t2 + 1];
    float d0x = att_dst2[t2], d0y = att_dst2[t2 + 1];
    float s1x = 0.f, s1y = 0.f, d1x = 0.f, d1y = 0.f;
    if (t2 == 0) { s1x = att_src2[8]; s1y = att_src2[9]; d1x = att_dst2[8]; d1y = att_dst2[9]; }
    float ps0 = a0c[0] * s0x + a0c[1] * s0y + a1c[0] * s1x + a1c[1] * s1y;
    float pd0 = a0c[0] * d0x + a0c[1] * d0y + a1c[0] * d1x + a1c[1] * d1y;
    float ps1 = a0c[2] * s0x + a0c[3] * s0y + a1c[2] * s1x + a1c[3] * s1y;
    float pd1 = a0c[2] * d0x + a0c[3] * d0y + a1c[2] * d1x + a1c[3] * d1y;
    ps0 += __shfl_xor_sync(0xffffffffu, ps0, 1);
    pd0 += __shfl_xor_sync(0xffffffffu, pd0, 1);
    ps1 += __shfl_xor_sync(0xffffffffu, ps1, 1);
    pd1 += __shfl_xor_sync(0xffffffffu, pd1, 1);
    ps0 += __shfl_xor_sync(0xffffffffu, ps0, 2);
    pd0 += __shfl_xor_sync(0xffffffffu, pd0, 2);
    ps1 += __shfl_xor_sync(0xffffffffu, ps1, 2);
    pd1 += __shfl_xor_sync(0xffffffffu, pd1, 2);
    if ((lane & 3) == 0) {
        if (r0 < NN) { g_as2[r0] = ps0; g_ad2[r0] = pd0; }
        if (r1 < NN) { g_as2[r1] = ps1; g_ad2[r1] = pd1; }
    }
}

// ---------------- layer-2 aggregation ---------------------------------------------
__global__ void k_agg2(const int* __restrict__ batch, const float* __restrict__ b2) {
    int warp = threadIdx.x >> 5;
    int lane = threadIdx.x & 31;
    int n = blockIdx.x * 8 + warp;
    if (n >= NN) return;
    const int half = lane >> 4;
    const int i = lane & 15;
    const float ad = g_ad2[n];
    float wsum = 0.f, acc = 0.f;
    if (half == 0) {
        float w = exp_lrelu(g_as2[n] + ad);
        wsum = w;
        acc = w * g_xh2[(size_t)n * 16 + i];
    }
    const int beg = g_off[n], end = g_off[n + 1];
    for (int e = beg + half; e < end; e += 2) {
        const int s = g_ssrc[e];
        const float we = exp_lrelu(g_as2[s] + ad);
        wsum += we;
        acc = fmaf(we, g_xh2[(size_t)s * 16 + i], acc);
    }
    wsum += __shfl_xor_sync(0xffffffffu, wsum, 16);
    acc += __shfl_xor_sync(0xffffffffu, acc, 16);
    if (half == 0 && i < CO) {
        float out = elu(acc / wsum + b2[i]);
        atomicAdd(&g_sums[batch[n] * CO + i], out);
    }
    if (lane == 0) atomicAdd(&g_cnt[batch[n]], 1.0f);
}

// ---------------- mean + log_softmax ----------------------------------------------
__global__ void k_final(float* __restrict__ out) {
    int g = threadIdx.x;
    if (g >= NG) return;
    float inv = 1.0f / fmaxf(g_cnt[g], 1.0f);
    float v[CO];
    float mx = -1e30f;
#pragma unroll
    for (int c = 0; c < CO; c++) {
        v[c] = g_sums[g * CO + c] * inv;
        mx = fmaxf(mx, v[c]);
    }
    float s = 0.f;
#pragma unroll
    for (int c = 0; c < CO; c++) s += __expf(v[c] - mx);
    float lse = logf(s) + mx;
#pragma unroll
    for (int c = 0; c < CO; c++) out[g * CO + c] = v[c] - lse;
}

// ---------------- launcher ----------------------------------------------------------
extern "C" void kernel_launch(void* const* d_in, const int* in_sizes, int n_in,
                              void* d_out, int out_size) {
    const float* x        = (const float*)d_in[0];
    const int*   ei       = (const int*)d_in[1];
    const int*   batch    = (const int*)d_in[2];
    const float* W1       = (const float*)d_in[3];
    const float* att_src1 = (const float*)d_in[4];
    const float* att_dst1 = (const float*)d_in[5];
    const float* b1       = (const float*)d_in[6];
    const float* W2       = (const float*)d_in[7];
    const float* att_src2 = (const float*)d_in[8];
    const float* att_dst2 = (const float*)d_in[9];
    const float* b2       = (const float*)d_in[10];
    float* out = (float*)d_out;
    const int E = in_sizes[1] / 2;

    static cudaStream_t s1 = nullptr;
    static cudaEvent_t e0 = nullptr, e1 = nullptr;
    if (!s1) {
        cudaStreamCreateWithFlags(&s1, cudaStreamNonBlocking);
        cudaEventCreateWithFlags(&e0, cudaEventDisableTiming);
        cudaEventCreateWithFlags(&e1, cudaEventDisableTiming);
        cudaFuncSetAttribute(k_gemm1, cudaFuncAttributeMaxDynamicSharedMemorySize, G1_SMEM);
        cudaFuncSetAttribute(k_gemm2, cudaFuncAttributeMaxDynamicSharedMemorySize, G2_SMEM);
    }

    cudaEventRecord(e0, 0);
    k_zero<<<(NN + 255) / 256, 256>>>();
    k_hist<<<(E + 255) / 256, 256>>>(ei, E);
    cudaStreamWaitEvent(s1, e0, 0);
    k_cvt_w<<<dim3(FIN / 32, HC / 32), dim3(32, 32), 0, s1>>>(W1);
    k_gemm1<<<(NN + 63) / 64, 256, G1_SMEM, s1>>>(x, att_src1, att_dst1);
    cudaEventRecord(e1, s1);
    k_scan1<<<NBLK, 256>>>();
    k_scan2<<<1, 256>>>();
    k_scan3<<<NBLK, 256>>>();
    k_scatter<<<(E + 255) / 256, 256>>>(ei, E);
    cudaStreamWaitEvent(0, e1, 0);
    k_agg1<<<NN / 16, 256>>>(b1);
    k_gemm2<<<(NN + 127) / 128, 256, G2_SMEM>>>(W2, att_src2, att_dst2);
    k_agg2<<<(NN + 7) / 8, 256>>>(batch, b2);
    k_final<<<1, NG>>>(out);
}